// round 3
// baseline (speedup 1.0000x reference)
#include <cuda_runtime.h>
#include <cuda_bf16.h>
#include <math.h>

// Problem constants
#define B_SZ   128
#define T_SEQ  256
#define EMB    384
#define NH     6
#define HD     64
#define WIN    64
#define M_ROWS (B_SZ * T_SEQ)        // 32768
#define QKV_N  (3 * EMB)             // 1152

// Scratch (no cudaMalloc allowed) — device globals.
__device__ float g_qkv[(size_t)M_ROWS * QKV_N];  // [M, 1152]
__device__ float g_y[(size_t)M_ROWS * EMB];      // [M, 384]

// ---------------------------------------------------------------------------
// GEMM: C[M,N] = A[M,384] @ B[384,N] + bias[N]
// Tiles: BM=64, BN=64, BK=16; 256 threads; 4x4 micro-tile per thread.
// M, N assumed multiples of 64 (32768, 1152, 384 all are). K = 384.
// ---------------------------------------------------------------------------
__global__ __launch_bounds__(256) void gemm_bias_kernel(
    const float* __restrict__ A, const float* __restrict__ Bm,
    const float* __restrict__ bias, float* __restrict__ C, int N)
{
    __shared__ float As[64][17];   // padded to avoid bank conflicts on column reads
    __shared__ float Bs[16][64];

    const int tid = threadIdx.x;
    const int tx  = tid & 15;       // 0..15  -> n micro-tile
    const int ty  = tid >> 4;       // 0..15  -> m micro-tile
    const int m0  = blockIdx.y << 6;
    const int n0  = blockIdx.x << 6;

    // A tile loader: row = tid>>2 (0..63), seg = tid&3 (4 floats each)
    const int a_row = tid >> 2;
    const int a_seg = tid & 3;
    const float* Aptr = A + (size_t)(m0 + a_row) * EMB + a_seg * 4;

    // B tile loader: row = tid>>4 (0..15), seg = tid&15 (4 floats each)
    const int b_row = tid >> 4;
    const int b_seg = tid & 15;
    const float* Bptr = Bm + (size_t)b_row * N + n0 + b_seg * 4;

    float acc[4][4];
    #pragma unroll
    for (int i = 0; i < 4; i++)
        #pragma unroll
        for (int j = 0; j < 4; j++) acc[i][j] = 0.f;

    for (int k0 = 0; k0 < EMB; k0 += 16) {
        float4 a4 = *(const float4*)(Aptr + k0);
        As[a_row][a_seg * 4 + 0] = a4.x;
        As[a_row][a_seg * 4 + 1] = a4.y;
        As[a_row][a_seg * 4 + 2] = a4.z;
        As[a_row][a_seg * 4 + 3] = a4.w;

        float4 b4 = *(const float4*)(Bptr + (size_t)k0 * N);
        *(float4*)&Bs[b_row][b_seg * 4] = b4;

        __syncthreads();

        #pragma unroll
        for (int kk = 0; kk < 16; kk++) {
            float4 bv = *(float4*)&Bs[kk][tx * 4];
            float a0 = As[ty * 4 + 0][kk];
            float a1 = As[ty * 4 + 1][kk];
            float a2 = As[ty * 4 + 2][kk];
            float a3 = As[ty * 4 + 3][kk];
            acc[0][0] += a0 * bv.x; acc[0][1] += a0 * bv.y; acc[0][2] += a0 * bv.z; acc[0][3] += a0 * bv.w;
            acc[1][0] += a1 * bv.x; acc[1][1] += a1 * bv.y; acc[1][2] += a1 * bv.z; acc[1][3] += a1 * bv.w;
            acc[2][0] += a2 * bv.x; acc[2][1] += a2 * bv.y; acc[2][2] += a2 * bv.z; acc[2][3] += a2 * bv.w;
            acc[3][0] += a3 * bv.x; acc[3][1] += a3 * bv.y; acc[3][2] += a3 * bv.z; acc[3][3] += a3 * bv.w;
        }
        __syncthreads();
    }

    float4 bb = *(const float4*)&bias[n0 + tx * 4];
    #pragma unroll
    for (int i = 0; i < 4; i++) {
        const int m = m0 + ty * 4 + i;
        float4 o;
        o.x = acc[i][0] + bb.x;
        o.y = acc[i][1] + bb.y;
        o.z = acc[i][2] + bb.z;
        o.w = acc[i][3] + bb.w;
        *(float4*)&C[(size_t)m * N + n0 + tx * 4] = o;
    }
}

// ---------------------------------------------------------------------------
// Banded causal attention.
// One block per (b, h, chunk of 64 queries). Keys needed: j in [q0-64, q0+63]
// (128 slots). Stages Q/K/V in SMEM, computes scores (q rows register-cached),
// softmax with 4-lane shuffle reduction, writes normalized weights to SMEM,
// then att @ V.
// Threads: 256 = 64 queries x 4 lanes.
// ---------------------------------------------------------------------------
#define QT 64
#define KT 128
#define ROWF 68   // 64 floats + 4 pad (272B rows, 16B aligned, conflict-free)
#define ATTP 129  // padded att row

__global__ __launch_bounds__(256, 1) void attn_kernel(
    const float* __restrict__ qkv, float* __restrict__ y)
{
    extern __shared__ float sm[];
    float* Ks  = sm;                     // KT * ROWF
    float* Vs  = Ks + KT * ROWF;         // KT * ROWF
    float* Qs  = Vs + KT * ROWF;         // QT * ROWF
    float* Att = Qs + QT * ROWF;         // QT * ATTP

    const int q0  = blockIdx.x * QT;
    const int h   = blockIdx.y;
    const int b   = blockIdx.z;
    const int tid = threadIdx.x;
    const int hoff = h * HD;

    const float* base = qkv + (size_t)b * T_SEQ * QKV_N;

    // Load K and V tiles (slot s <-> token j = q0 - 64 + s), zero out-of-range.
    for (int idx = tid; idx < KT * 16; idx += 256) {
        const int s = idx >> 4, f = idx & 15;
        const int j = q0 - WIN + s;
        float4 kv, vv;
        if (j >= 0 && j < T_SEQ) {
            const float* row = base + (size_t)j * QKV_N;
            kv = *(const float4*)(row + EMB     + hoff + f * 4);
            vv = *(const float4*)(row + 2 * EMB + hoff + f * 4);
        } else {
            kv = make_float4(0.f, 0.f, 0.f, 0.f);
            vv = kv;
        }
        *(float4*)(Ks + s * ROWF + f * 4) = kv;
        *(float4*)(Vs + s * ROWF + f * 4) = vv;
    }
    // Load Q tile.
    for (int idx = tid; idx < QT * 16; idx += 256) {
        const int qi = idx >> 4, f = idx & 15;
        const float* row = base + (size_t)(q0 + qi) * QKV_N;
        *(float4*)(Qs + qi * ROWF + f * 4) = *(const float4*)(row + hoff + f * 4);
    }
    __syncthreads();

    const int qi = tid >> 2;   // 0..63
    const int kg = tid & 3;    // 0..3  (32 key slots each)

    // Register-cache this thread's q row.
    float4 qr[16];
    #pragma unroll
    for (int f = 0; f < 16; f++) qr[f] = *(float4*)(Qs + qi * ROWF + f * 4);

    // Valid key slots for query i = q0+qi:  s in [max(qi, 64-q0), qi+64]
    const int smin = max(qi, WIN - q0);
    const int smax = qi + WIN;

    float sc[32];
    float mloc = -1e30f;
    #pragma unroll 4
    for (int si = 0; si < 32; si++) {
        const int s = kg * 32 + si;
        const float4* kr = (const float4*)(Ks + s * ROWF);
        float acc = 0.f;
        #pragma unroll
        for (int f = 0; f < 16; f++) {
            float4 k4 = kr[f];
            acc += qr[f].x * k4.x + qr[f].y * k4.y + qr[f].z * k4.z + qr[f].w * k4.w;
        }
        const bool valid = (s >= smin) && (s <= smax);
        sc[si] = valid ? acc * 0.125f : -1e30f;   // 1/sqrt(64) = 0.125
        mloc = fmaxf(mloc, sc[si]);
    }
    // reduce max / sum across the 4 lanes of this query group
    mloc = fmaxf(mloc, __shfl_xor_sync(0xffffffffu, mloc, 1));
    mloc = fmaxf(mloc, __shfl_xor_sync(0xffffffffu, mloc, 2));
    float ssum = 0.f;
    #pragma unroll
    for (int si = 0; si < 32; si++) {
        float e = expf(sc[si] - mloc);  // invalid -> exp(-huge) = 0
        sc[si] = e;
        ssum += e;
    }
    ssum += __shfl_xor_sync(0xffffffffu, ssum, 1);
    ssum += __shfl_xor_sync(0xffffffffu, ssum, 2);
    const float inv = 1.f / ssum;

    #pragma unroll
    for (int si = 0; si < 32; si++)
        Att[qi * ATTP + kg * 32 + si] = sc[si] * inv;
    __syncthreads();

    // Output: thread (qi, dg=kg) handles d = dg*16 .. dg*16+15
    float4 oacc[4];
    #pragma unroll
    for (int d4 = 0; d4 < 4; d4++) oacc[d4] = make_float4(0.f, 0.f, 0.f, 0.f);

    const float* arow = Att + qi * ATTP;
    #pragma unroll 4
    for (int s = 0; s < KT; s++) {
        const float a = arow[s];
        const float4* vr = (const float4*)(Vs + s * ROWF + kg * 16);
        #pragma unroll
        for (int d4 = 0; d4 < 4; d4++) {
            float4 v = vr[d4];
            oacc[d4].x += a * v.x;
            oacc[d4].y += a * v.y;
            oacc[d4].z += a * v.z;
            oacc[d4].w += a * v.w;
        }
    }

    float* yrow = y + ((size_t)(b * T_SEQ + q0 + qi)) * EMB + hoff + kg * 16;
    #pragma unroll
    for (int d4 = 0; d4 < 4; d4++)
        *(float4*)(yrow + d4 * 4) = oacc[d4];
}

// ---------------------------------------------------------------------------
// Launch
// ---------------------------------------------------------------------------
extern "C" void kernel_launch(void* const* d_in, const int* in_sizes, int n_in,
                              void* d_out, int out_size)
{
    const float* x      = (const float*)d_in[0];  // [128,256,384]
    const float* W_attn = (const float*)d_in[1];  // [384,1152]
    const float* b_attn = (const float*)d_in[2];  // [1152]
    const float* W_proj = (const float*)d_in[3];  // [384,384]
    const float* b_proj = (const float*)d_in[4];  // [384]
    float* out = (float*)d_out;                   // [128,256,384]

    float *qkv_ptr = nullptr, *y_ptr = nullptr;
    cudaGetSymbolAddress((void**)&qkv_ptr, g_qkv);
    cudaGetSymbolAddress((void**)&y_ptr, g_y);

    // 1) qkv = x @ W_attn + b_attn
    {
        dim3 grid(QKV_N / 64, M_ROWS / 64);
        gemm_bias_kernel<<<grid, 256>>>(x, W_attn, b_attn, qkv_ptr, QKV_N);
    }

    // 2) banded attention -> g_y
    {
        const int smem_bytes = (2 * KT * ROWF + QT * ROWF + QT * ATTP) * (int)sizeof(float);
        cudaFuncSetAttribute(attn_kernel, cudaFuncAttributeMaxDynamicSharedMemorySize, smem_bytes);
        dim3 grid(T_SEQ / QT, NH, B_SZ);
        attn_kernel<<<grid, 256, smem_bytes>>>(qkv_ptr, y_ptr);
    }

    // 3) out = y @ W_proj + b_proj
    {
        dim3 grid(EMB / 64, M_ROWS / 64);
        gemm_bias_kernel<<<grid, 256>>>(y_ptr, W_proj, b_proj, out, EMB);
    }
}

// round 6
// speedup vs baseline: 2.3475x; 2.3475x over previous
#include <cuda_runtime.h>
#include <cuda_bf16.h>
#include <math.h>
#include <stdint.h>

// Problem constants
#define B_SZ   128
#define T_SEQ  256
#define EMB    384
#define NH     6
#define HD     64
#define WIN    64
#define M_ROWS (B_SZ * T_SEQ)        // 32768
#define QKV_N  (3 * EMB)             // 1152

// Scratch (no cudaMalloc allowed) — device globals.
__device__ float g_qkv[(size_t)M_ROWS * QKV_N];  // [M, 1152]
__device__ float g_y[(size_t)M_ROWS * EMB];      // [M, 384]

// ---------------------------------------------------------------------------
// tf32 helpers
// ---------------------------------------------------------------------------
__device__ __forceinline__ float to_tf32(float x) {
    uint32_t u;
    asm("cvt.rna.tf32.f32 %0, %1;" : "=r"(u) : "f"(x));
    return __uint_as_float(u);
}

__device__ __forceinline__ void mma_tf32(float c[4],
    uint32_t a0, uint32_t a1, uint32_t a2, uint32_t a3,
    uint32_t b0, uint32_t b1)
{
    asm volatile(
        "mma.sync.aligned.m16n8k8.row.col.f32.tf32.tf32.f32 "
        "{%0,%1,%2,%3}, {%4,%5,%6,%7}, {%8,%9}, {%0,%1,%2,%3};"
        : "+f"(c[0]), "+f"(c[1]), "+f"(c[2]), "+f"(c[3])
        : "r"(a0), "r"(a1), "r"(a2), "r"(a3), "r"(b0), "r"(b1));
}

// ---------------------------------------------------------------------------
// tf32 tensor-core GEMM: C[M,N] = A[M,384] @ B[384,N] + bias[N]
// BM=128, BN=128, BK=16, 256 threads (8 warps as 2x4), warp tile 64x32.
// A smem: [m][k] stride 20 (frag loads conflict-free).
// B smem: [k][n] stride 136 (frag loads conflict-free).
// K = 384 fixed (lda = 384 for both GEMMs). N in {1152, 384}.
// ---------------------------------------------------------------------------
#define GBM 128
#define GBN 128
#define GBK 16
#define AS_ST 20
#define BS_ST 136

__global__ __launch_bounds__(256) void gemm_tf32_kernel(
    const float* __restrict__ A, const float* __restrict__ Bm,
    const float* __restrict__ bias, float* __restrict__ C, int N)
{
    __shared__ float As[GBM][AS_ST];   // [m][k0..15]
    __shared__ float Bs[GBK][BS_ST];   // [k][n0..127]

    const int tid  = threadIdx.x;
    const int lane = tid & 31;
    const int wid  = tid >> 5;
    const int warp_m = wid >> 2;   // 0..1 -> 64 rows each
    const int warp_n = wid & 3;    // 0..3 -> 32 cols each
    const int m0 = blockIdx.y * GBM;
    const int n0 = blockIdx.x * GBN;

    // A loader: row = (tid>>2) (+64), k-seg = (tid&3)*4
    const int ar = tid >> 2;          // 0..63
    const int ak = (tid & 3) * 4;     // 0,4,8,12
    // B loader: k-row = tid>>4, n-seg = (tid&15)*4 (+64)
    const int bk = tid >> 4;          // 0..15
    const int bn = (tid & 15) * 4;

    const float* Ag = A + (size_t)m0 * EMB;
    const float* Bg = Bm + n0;

    float c[4][4][4];
    #pragma unroll
    for (int mt = 0; mt < 4; mt++)
        #pragma unroll
        for (int nt = 0; nt < 4; nt++)
            #pragma unroll
            for (int i = 0; i < 4; i++) c[mt][nt][i] = 0.f;

    // preload tile 0
    float4 ar0 = *(const float4*)(Ag + (size_t)ar * EMB + ak);
    float4 ar1 = *(const float4*)(Ag + (size_t)(ar + 64) * EMB + ak);
    float4 br0 = *(const float4*)(Bg + (size_t)bk * N + bn);
    float4 br1 = *(const float4*)(Bg + (size_t)bk * N + bn + 64);

    const int lg = lane >> 2;   // groupID 0..7
    const int lt = lane & 3;    // threadID in group

    #pragma unroll 1
    for (int kt = 0; kt < EMB / GBK; kt++) {
        // stage to smem with tf32 rounding
        {
            float4 t;
            t.x = to_tf32(ar0.x); t.y = to_tf32(ar0.y); t.z = to_tf32(ar0.z); t.w = to_tf32(ar0.w);
            *(float4*)&As[ar][ak] = t;
            t.x = to_tf32(ar1.x); t.y = to_tf32(ar1.y); t.z = to_tf32(ar1.z); t.w = to_tf32(ar1.w);
            *(float4*)&As[ar + 64][ak] = t;
            t.x = to_tf32(br0.x); t.y = to_tf32(br0.y); t.z = to_tf32(br0.z); t.w = to_tf32(br0.w);
            *(float4*)&Bs[bk][bn] = t;
            t.x = to_tf32(br1.x); t.y = to_tf32(br1.y); t.z = to_tf32(br1.z); t.w = to_tf32(br1.w);
            *(float4*)&Bs[bk][bn + 64] = t;
        }
        __syncthreads();

        // prefetch next tile
        if (kt < EMB / GBK - 1) {
            const int k0 = (kt + 1) * GBK;
            ar0 = *(const float4*)(Ag + (size_t)ar * EMB + k0 + ak);
            ar1 = *(const float4*)(Ag + (size_t)(ar + 64) * EMB + k0 + ak);
            br0 = *(const float4*)(Bg + (size_t)(k0 + bk) * N + bn);
            br1 = *(const float4*)(Bg + (size_t)(k0 + bk) * N + bn + 64);
        }

        // compute: two k8 steps
        #pragma unroll
        for (int ks = 0; ks < GBK; ks += 8) {
            uint32_t bf[4][2];
            #pragma unroll
            for (int nt = 0; nt < 4; nt++) {
                const int nb = warp_n * 32 + nt * 8 + lg;
                bf[nt][0] = __float_as_uint(Bs[ks + lt][nb]);
                bf[nt][1] = __float_as_uint(Bs[ks + 4 + lt][nb]);
            }
            #pragma unroll
            for (int mt = 0; mt < 4; mt++) {
                const int mb = warp_m * 64 + mt * 16 + lg;
                uint32_t a0 = __float_as_uint(As[mb][ks + lt]);
                uint32_t a1 = __float_as_uint(As[mb + 8][ks + lt]);
                uint32_t a2 = __float_as_uint(As[mb][ks + 4 + lt]);
                uint32_t a3 = __float_as_uint(As[mb + 8][ks + 4 + lt]);
                #pragma unroll
                for (int nt = 0; nt < 4; nt++)
                    mma_tf32(c[mt][nt], a0, a1, a2, a3, bf[nt][0], bf[nt][1]);
            }
        }
        __syncthreads();
    }

    // epilogue: add bias, store
    #pragma unroll
    for (int mt = 0; mt < 4; mt++) {
        const int row = m0 + warp_m * 64 + mt * 16 + lg;
        #pragma unroll
        for (int nt = 0; nt < 4; nt++) {
            const int col = n0 + warp_n * 32 + nt * 8 + lt * 2;
            const float b0 = bias[col], b1 = bias[col + 1];
            float2 v0 = make_float2(c[mt][nt][0] + b0, c[mt][nt][1] + b1);
            float2 v1 = make_float2(c[mt][nt][2] + b0, c[mt][nt][3] + b1);
            *(float2*)&C[(size_t)row * N + col]       = v0;
            *(float2*)&C[(size_t)(row + 8) * N + col] = v1;
        }
    }
}

// ---------------------------------------------------------------------------
// Banded causal attention (register-blocked).
// One block per (b, h, chunk of 64 queries). 256 threads.
// Score phase: thread = (qg = tid>>4, kl = tid&15): 4 queries x 8 key slots,
// K float4 reused across 4 q-rows (10.7 FMA / LDS).
// Softmax reduced over the 16 kl lanes (shfl within half-warp).
// AV phase: thread = (qi = tid>>2, dg = tid&3).
// ---------------------------------------------------------------------------
#define QT 64
#define KT 128
#define ROWF 68   // 64 floats + 4 pad
#define ATTP 132  // padded att row stride

__global__ __launch_bounds__(256, 1) void attn_kernel(
    const float* __restrict__ qkv, float* __restrict__ y)
{
    extern __shared__ float sm[];
    float* Ks  = sm;                     // KT * ROWF
    float* Vs  = Ks + KT * ROWF;         // KT * ROWF
    float* Qs  = Vs + KT * ROWF;         // QT * ROWF
    float* Att = Qs + QT * ROWF;         // QT * ATTP

    const int q0  = blockIdx.x * QT;
    const int h   = blockIdx.y;
    const int b   = blockIdx.z;
    const int tid = threadIdx.x;
    const int hoff = h * HD;

    const float* base = qkv + (size_t)b * T_SEQ * QKV_N;

    // Load K and V tiles (slot s <-> token j = q0 - 64 + s), zero out-of-range.
    for (int idx = tid; idx < KT * 16; idx += 256) {
        const int s = idx >> 4, f = idx & 15;
        const int j = q0 - WIN + s;
        float4 kv, vv;
        if (j >= 0 && j < T_SEQ) {
            const float* row = base + (size_t)j * QKV_N;
            kv = *(const float4*)(row + EMB     + hoff + f * 4);
            vv = *(const float4*)(row + 2 * EMB + hoff + f * 4);
        } else {
            kv = make_float4(0.f, 0.f, 0.f, 0.f);
            vv = kv;
        }
        *(float4*)(Ks + s * ROWF + f * 4) = kv;
        *(float4*)(Vs + s * ROWF + f * 4) = vv;
    }
    // Load Q tile.
    for (int idx = tid; idx < QT * 16; idx += 256) {
        const int qi = idx >> 4, f = idx & 15;
        const float* row = base + (size_t)(q0 + qi) * QKV_N;
        *(float4*)(Qs + qi * ROWF + f * 4) = *(const float4*)(row + hoff + f * 4);
    }
    __syncthreads();

    // ---- score phase ----
    const int qg = tid >> 4;   // 0..15 -> queries qg*4..qg*4+3
    const int kl = tid & 15;   // 0..15 -> slots si*16+kl

    float acc[4][8];
    #pragma unroll
    for (int qq = 0; qq < 4; qq++)
        #pragma unroll
        for (int si = 0; si < 8; si++) acc[qq][si] = 0.f;

    #pragma unroll
    for (int f = 0; f < 16; f++) {
        float4 q4[4];
        #pragma unroll
        for (int qq = 0; qq < 4; qq++)
            q4[qq] = *(float4*)(Qs + (qg * 4 + qq) * ROWF + f * 4);
        #pragma unroll
        for (int si = 0; si < 8; si++) {
            float4 k4 = *(float4*)(Ks + (si * 16 + kl) * ROWF + f * 4);
            #pragma unroll
            for (int qq = 0; qq < 4; qq++) {
                acc[qq][si] += q4[qq].x * k4.x + q4[qq].y * k4.y
                             + q4[qq].z * k4.z + q4[qq].w * k4.w;
            }
        }
    }

    // ---- mask + softmax (per query row, reduced over 16 kl lanes) ----
    #pragma unroll
    for (int qq = 0; qq < 4; qq++) {
        const int qi = qg * 4 + qq;
        const int smin = max(qi, WIN - q0);
        const int smax = qi + WIN;
        float m = -1e30f;
        #pragma unroll
        for (int si = 0; si < 8; si++) {
            const int s = si * 16 + kl;
            const bool v = (s >= smin) && (s <= smax);
            float t = v ? acc[qq][si] * 0.125f : -1e30f;
            acc[qq][si] = t;
            m = fmaxf(m, t);
        }
        m = fmaxf(m, __shfl_xor_sync(0xffffffffu, m, 1));
        m = fmaxf(m, __shfl_xor_sync(0xffffffffu, m, 2));
        m = fmaxf(m, __shfl_xor_sync(0xffffffffu, m, 4));
        m = fmaxf(m, __shfl_xor_sync(0xffffffffu, m, 8));
        float ssum = 0.f;
        #pragma unroll
        for (int si = 0; si < 8; si++) {
            float e = __expf(acc[qq][si] - m);
            acc[qq][si] = e;
            ssum += e;
        }
        ssum += __shfl_xor_sync(0xffffffffu, ssum, 1);
        ssum += __shfl_xor_sync(0xffffffffu, ssum, 2);
        ssum += __shfl_xor_sync(0xffffffffu, ssum, 4);
        ssum += __shfl_xor_sync(0xffffffffu, ssum, 8);
        const float inv = 1.f / ssum;
        #pragma unroll
        for (int si = 0; si < 8; si++)
            Att[qi * ATTP + si * 16 + kl] = acc[qq][si] * inv;
    }
    __syncthreads();

    // ---- AV phase ----
    const int qi = tid >> 2;   // 0..63
    const int dg = tid & 3;    // 0..3 -> d = dg*16..+15

    float4 o[4];
    #pragma unroll
    for (int j = 0; j < 4; j++) o[j] = make_float4(0.f, 0.f, 0.f, 0.f);

    const float* arow = Att + qi * ATTP;
    #pragma unroll 4
    for (int s = 0; s < KT; s++) {
        const float a = arow[s];
        const float4* vr = (const float4*)(Vs + s * ROWF + dg * 16);
        #pragma unroll
        for (int j = 0; j < 4; j++) {
            float4 v = vr[j];
            o[j].x += a * v.x; o[j].y += a * v.y;
            o[j].z += a * v.z; o[j].w += a * v.w;
        }
    }

    float* yrow = y + ((size_t)(b * T_SEQ + q0 + qi)) * EMB + hoff + dg * 16;
    #pragma unroll
    for (int j = 0; j < 4; j++)
        *(float4*)(yrow + j * 4) = o[j];
}

// ---------------------------------------------------------------------------
// Launch
// ---------------------------------------------------------------------------
extern "C" void kernel_launch(void* const* d_in, const int* in_sizes, int n_in,
                              void* d_out, int out_size)
{
    const float* x      = (const float*)d_in[0];  // [128,256,384]
    const float* W_attn = (const float*)d_in[1];  // [384,1152]
    const float* b_attn = (const float*)d_in[2];  // [1152]
    const float* W_proj = (const float*)d_in[3];  // [384,384]
    const float* b_proj = (const float*)d_in[4];  // [384]
    float* out = (float*)d_out;                   // [128,256,384]

    float *qkv_ptr = nullptr, *y_ptr = nullptr;
    cudaGetSymbolAddress((void**)&qkv_ptr, g_qkv);
    cudaGetSymbolAddress((void**)&y_ptr, g_y);

    // 1) qkv = x @ W_attn + b_attn   (tf32 tensor cores)
    {
        dim3 grid(QKV_N / GBN, M_ROWS / GBM);
        gemm_tf32_kernel<<<grid, 256>>>(x, W_attn, b_attn, qkv_ptr, QKV_N);
    }

    // 2) banded attention -> g_y
    {
        const int smem_bytes = (2 * KT * ROWF + QT * ROWF + QT * ATTP) * (int)sizeof(float);
        cudaFuncSetAttribute(attn_kernel, cudaFuncAttributeMaxDynamicSharedMemorySize, smem_bytes);
        dim3 grid(T_SEQ / QT, NH, B_SZ);
        attn_kernel<<<grid, 256, smem_bytes>>>(qkv_ptr, y_ptr);
    }

    // 3) out = y @ W_proj + b_proj   (tf32 tensor cores)
    {
        dim3 grid(EMB / GBN, M_ROWS / GBM);
        gemm_tf32_kernel<<<grid, 256>>>(y_ptr, W_proj, b_proj, out, EMB);
    }
}

// round 7
// speedup vs baseline: 4.5323x; 1.9307x over previous
#include <cuda_runtime.h>
#include <cuda_bf16.h>
#include <math.h>
#include <stdint.h>

// Problem constants
#define B_SZ   128
#define T_SEQ  256
#define EMB    384
#define NH     6
#define HD     64
#define WIN    64
#define M_ROWS (B_SZ * T_SEQ)        // 32768
#define QKV_N  (3 * EMB)             // 1152

// Scratch (no cudaMalloc allowed) — device globals.
__device__ float g_qkv[(size_t)M_ROWS * QKV_N];  // [M, 1152]
__device__ float g_y[(size_t)M_ROWS * EMB];      // [M, 384]

// ---------------------------------------------------------------------------
// tf32 helpers
// ---------------------------------------------------------------------------
__device__ __forceinline__ float to_tf32(float x) {
    uint32_t u;
    asm("cvt.rna.tf32.f32 %0, %1;" : "=r"(u) : "f"(x));
    return __uint_as_float(u);
}

__device__ __forceinline__ void mma_tf32(float c[4],
    uint32_t a0, uint32_t a1, uint32_t a2, uint32_t a3,
    uint32_t b0, uint32_t b1)
{
    asm volatile(
        "mma.sync.aligned.m16n8k8.row.col.f32.tf32.tf32.f32 "
        "{%0,%1,%2,%3}, {%4,%5,%6,%7}, {%8,%9}, {%0,%1,%2,%3};"
        : "+f"(c[0]), "+f"(c[1]), "+f"(c[2]), "+f"(c[3])
        : "r"(a0), "r"(a1), "r"(a2), "r"(a3), "r"(b0), "r"(b1));
}

// ---------------------------------------------------------------------------
// tf32 tensor-core GEMM: C[M,N] = A[M,384] @ B[384,N] + bias[N]
// (unchanged from round 6 — 252us for N=1152)
// ---------------------------------------------------------------------------
#define GBM 128
#define GBN 128
#define GBK 16
#define AS_ST 20
#define BS_ST 136

__global__ __launch_bounds__(256) void gemm_tf32_kernel(
    const float* __restrict__ A, const float* __restrict__ Bm,
    const float* __restrict__ bias, float* __restrict__ C, int N)
{
    __shared__ float As[GBM][AS_ST];
    __shared__ float Bs[GBK][BS_ST];

    const int tid  = threadIdx.x;
    const int lane = tid & 31;
    const int wid  = tid >> 5;
    const int warp_m = wid >> 2;
    const int warp_n = wid & 3;
    const int m0 = blockIdx.y * GBM;
    const int n0 = blockIdx.x * GBN;

    const int ar = tid >> 2;
    const int ak = (tid & 3) * 4;
    const int bk = tid >> 4;
    const int bn = (tid & 15) * 4;

    const float* Ag = A + (size_t)m0 * EMB;
    const float* Bg = Bm + n0;

    float c[4][4][4];
    #pragma unroll
    for (int mt = 0; mt < 4; mt++)
        #pragma unroll
        for (int nt = 0; nt < 4; nt++)
            #pragma unroll
            for (int i = 0; i < 4; i++) c[mt][nt][i] = 0.f;

    float4 ar0 = *(const float4*)(Ag + (size_t)ar * EMB + ak);
    float4 ar1 = *(const float4*)(Ag + (size_t)(ar + 64) * EMB + ak);
    float4 br0 = *(const float4*)(Bg + (size_t)bk * N + bn);
    float4 br1 = *(const float4*)(Bg + (size_t)bk * N + bn + 64);

    const int lg = lane >> 2;
    const int lt = lane & 3;

    #pragma unroll 1
    for (int kt = 0; kt < EMB / GBK; kt++) {
        {
            float4 t;
            t.x = to_tf32(ar0.x); t.y = to_tf32(ar0.y); t.z = to_tf32(ar0.z); t.w = to_tf32(ar0.w);
            *(float4*)&As[ar][ak] = t;
            t.x = to_tf32(ar1.x); t.y = to_tf32(ar1.y); t.z = to_tf32(ar1.z); t.w = to_tf32(ar1.w);
            *(float4*)&As[ar + 64][ak] = t;
            t.x = to_tf32(br0.x); t.y = to_tf32(br0.y); t.z = to_tf32(br0.z); t.w = to_tf32(br0.w);
            *(float4*)&Bs[bk][bn] = t;
            t.x = to_tf32(br1.x); t.y = to_tf32(br1.y); t.z = to_tf32(br1.z); t.w = to_tf32(br1.w);
            *(float4*)&Bs[bk][bn + 64] = t;
        }
        __syncthreads();

        if (kt < EMB / GBK - 1) {
            const int k0 = (kt + 1) * GBK;
            ar0 = *(const float4*)(Ag + (size_t)ar * EMB + k0 + ak);
            ar1 = *(const float4*)(Ag + (size_t)(ar + 64) * EMB + k0 + ak);
            br0 = *(const float4*)(Bg + (size_t)(k0 + bk) * N + bn);
            br1 = *(const float4*)(Bg + (size_t)(k0 + bk) * N + bn + 64);
        }

        #pragma unroll
        for (int ks = 0; ks < GBK; ks += 8) {
            uint32_t bf[4][2];
            #pragma unroll
            for (int nt = 0; nt < 4; nt++) {
                const int nb = warp_n * 32 + nt * 8 + lg;
                bf[nt][0] = __float_as_uint(Bs[ks + lt][nb]);
                bf[nt][1] = __float_as_uint(Bs[ks + 4 + lt][nb]);
            }
            #pragma unroll
            for (int mt = 0; mt < 4; mt++) {
                const int mb = warp_m * 64 + mt * 16 + lg;
                uint32_t a0 = __float_as_uint(As[mb][ks + lt]);
                uint32_t a1 = __float_as_uint(As[mb + 8][ks + lt]);
                uint32_t a2 = __float_as_uint(As[mb][ks + 4 + lt]);
                uint32_t a3 = __float_as_uint(As[mb + 8][ks + 4 + lt]);
                #pragma unroll
                for (int nt = 0; nt < 4; nt++)
                    mma_tf32(c[mt][nt], a0, a1, a2, a3, bf[nt][0], bf[nt][1]);
            }
        }
        __syncthreads();
    }

    #pragma unroll
    for (int mt = 0; mt < 4; mt++) {
        const int row = m0 + warp_m * 64 + mt * 16 + lg;
        #pragma unroll
        for (int nt = 0; nt < 4; nt++) {
            const int col = n0 + warp_n * 32 + nt * 8 + lt * 2;
            const float b0 = bias[col], b1 = bias[col + 1];
            float2 v0 = make_float2(c[mt][nt][0] + b0, c[mt][nt][1] + b1);
            float2 v1 = make_float2(c[mt][nt][2] + b0, c[mt][nt][3] + b1);
            *(float2*)&C[(size_t)row * N + col]       = v0;
            *(float2*)&C[(size_t)(row + 8) * N + col] = v1;
        }
    }
}

// ---------------------------------------------------------------------------
// Banded causal attention — tensor-core version.
// One block per (b, h, 64-query chunk). 256 threads (8 warps).
// Phase 1: S[64,128] = Q @ K^T via tf32 mma (warp = m16 x n64; 4 mt x 2 nh).
// Phase 2: fp32 masked softmax on S in smem.
// Phase 3: O[64,64] = P @ V via tf32 mma; V transposed to [d][s] at load.
// Smem: Vt[64][132] | union( Qs[64][68] + Ks[128][68] , Ss[64][136] ).
// Total 84 KB -> 2 blocks/SM.
// ---------------------------------------------------------------------------
#define QT 64
#define KT 128
#define QS_ST 68    // 68 % 32 == 4 -> frag banks 4*lg+lt distinct
#define KS_ST 68
#define VT_ST 132   // 132 % 32 == 4
#define SS_ST 136   // 136 % 32 == 8 -> frag banks 8*lg+lt, write banks 8*lg+2*lt

#define SM_VT   0
#define SM_Q    (64 * VT_ST)
#define SM_K    (SM_Q + QT * QS_ST)
#define SM_S    SM_Q
#define SM_TOTF (SM_K + KT * KS_ST)   // 21504 floats = 84 KB

__global__ __launch_bounds__(256, 2) void attn_kernel(
    const float* __restrict__ qkv, float* __restrict__ y)
{
    extern __shared__ float sm[];
    float* Vt = sm + SM_VT;   // [d=64][s=128], stride VT_ST
    float* Qs = sm + SM_Q;    // [q=64][d=64], stride QS_ST
    float* Ks = sm + SM_K;    // [s=128][d=64], stride KS_ST
    float* Ss = sm + SM_S;    // [q=64][s=128], stride SS_ST (aliases Qs/Ks)

    const int q0  = blockIdx.x * QT;
    const int h   = blockIdx.y;
    const int b   = blockIdx.z;
    const int tid = threadIdx.x;
    const int hoff = h * HD;

    const float* base = qkv + (size_t)b * T_SEQ * QKV_N;

    // ---- load K (row-major), V (transposed), Q; tf32-round everything ----
    for (int idx = tid; idx < KT * 16; idx += 256) {
        const int s = idx >> 4, f = idx & 15;
        const int j = q0 - WIN + s;
        float4 kv, vv;
        if (j >= 0 && j < T_SEQ) {
            const float* row = base + (size_t)j * QKV_N;
            kv = *(const float4*)(row + EMB     + hoff + f * 4);
            vv = *(const float4*)(row + 2 * EMB + hoff + f * 4);
        } else {
            kv = make_float4(0.f, 0.f, 0.f, 0.f);
            vv = kv;
        }
        float4 t;
        t.x = to_tf32(kv.x); t.y = to_tf32(kv.y); t.z = to_tf32(kv.z); t.w = to_tf32(kv.w);
        *(float4*)(Ks + s * KS_ST + f * 4) = t;
        Vt[(f * 4 + 0) * VT_ST + s] = to_tf32(vv.x);
        Vt[(f * 4 + 1) * VT_ST + s] = to_tf32(vv.y);
        Vt[(f * 4 + 2) * VT_ST + s] = to_tf32(vv.z);
        Vt[(f * 4 + 3) * VT_ST + s] = to_tf32(vv.w);
    }
    for (int idx = tid; idx < QT * 16; idx += 256) {
        const int qi = idx >> 4, f = idx & 15;
        const float* row = base + (size_t)(q0 + qi) * QKV_N;
        float4 q4 = *(const float4*)(row + hoff + f * 4);
        float4 t;
        t.x = to_tf32(q4.x); t.y = to_tf32(q4.y); t.z = to_tf32(q4.z); t.w = to_tf32(q4.w);
        *(float4*)(Qs + qi * QS_ST + f * 4) = t;
    }
    __syncthreads();

    const int lane = tid & 31;
    const int wid  = tid >> 5;
    const int lg = lane >> 2;   // 0..7
    const int lt = lane & 3;    // 0..3
    const int mt = wid & 3;     // m-tile: rows mt*16 .. +15
    const int nh = wid >> 2;    // n-half

    // ---- phase 1: S = Q @ K^T  (warp: m16 x n64, 8 k8 steps) ----
    float sc[8][4];
    #pragma unroll
    for (int nt = 0; nt < 8; nt++)
        #pragma unroll
        for (int i = 0; i < 4; i++) sc[nt][i] = 0.f;

    const int mrow = mt * 16 + lg;
    #pragma unroll
    for (int k0 = 0; k0 < HD; k0 += 8) {
        uint32_t a0 = __float_as_uint(Qs[mrow * QS_ST + k0 + lt]);
        uint32_t a1 = __float_as_uint(Qs[(mrow + 8) * QS_ST + k0 + lt]);
        uint32_t a2 = __float_as_uint(Qs[mrow * QS_ST + k0 + 4 + lt]);
        uint32_t a3 = __float_as_uint(Qs[(mrow + 8) * QS_ST + k0 + 4 + lt]);
        #pragma unroll
        for (int nt = 0; nt < 8; nt++) {
            const int nb = nh * 64 + nt * 8 + lg;
            uint32_t b0 = __float_as_uint(Ks[nb * KS_ST + k0 + lt]);
            uint32_t b1 = __float_as_uint(Ks[nb * KS_ST + k0 + 4 + lt]);
            mma_tf32(sc[nt], a0, a1, a2, a3, b0, b1);
        }
    }
    __syncthreads();   // done reading Qs/Ks; Ss may now overwrite them

    // write S fragments to smem (rows mrow, mrow+8; cols nh*64+nt*8+2lt)
    #pragma unroll
    for (int nt = 0; nt < 8; nt++) {
        const int col = nh * 64 + nt * 8 + lt * 2;
        *(float2*)(Ss + mrow * SS_ST + col)       = make_float2(sc[nt][0], sc[nt][1]);
        *(float2*)(Ss + (mrow + 8) * SS_ST + col) = make_float2(sc[nt][2], sc[nt][3]);
    }
    __syncthreads();

    // ---- phase 2: masked softmax, row-wise. thread = (qi=tid>>2, kg=tid&3),
    // slots s = 4*si + kg (conflict-free: bank = 8*qi + 4*si + kg) ----
    {
        const int qi = tid >> 2;
        const int kg = tid & 3;
        const int smin = max(qi, WIN - q0);
        const int smax = qi + WIN;
        float* srow = Ss + qi * SS_ST;

        float v[32];
        float m = -1e30f;
        #pragma unroll
        for (int si = 0; si < 32; si++) {
            const int s = si * 4 + kg;
            const bool ok = (s >= smin) && (s <= smax);
            float t = ok ? srow[s] * 0.125f : -1e30f;
            v[si] = t;
            m = fmaxf(m, t);
        }
        m = fmaxf(m, __shfl_xor_sync(0xffffffffu, m, 1));
        m = fmaxf(m, __shfl_xor_sync(0xffffffffu, m, 2));
        float ssum = 0.f;
        #pragma unroll
        for (int si = 0; si < 32; si++) {
            float e = __expf(v[si] - m);
            v[si] = e;
            ssum += e;
        }
        ssum += __shfl_xor_sync(0xffffffffu, ssum, 1);
        ssum += __shfl_xor_sync(0xffffffffu, ssum, 2);
        const float inv = 1.f / ssum;
        #pragma unroll
        for (int si = 0; si < 32; si++)
            srow[si * 4 + kg] = to_tf32(v[si] * inv);
    }
    __syncthreads();

    // ---- phase 3: O = P @ V  (warp: m16 x n32, 16 k8 steps; B from Vt[d][s]) ----
    float oc[4][4];
    #pragma unroll
    for (int nt = 0; nt < 4; nt++)
        #pragma unroll
        for (int i = 0; i < 4; i++) oc[nt][i] = 0.f;

    #pragma unroll
    for (int k0 = 0; k0 < KT; k0 += 8) {
        uint32_t a0 = __float_as_uint(Ss[mrow * SS_ST + k0 + lt]);
        uint32_t a1 = __float_as_uint(Ss[(mrow + 8) * SS_ST + k0 + lt]);
        uint32_t a2 = __float_as_uint(Ss[mrow * SS_ST + k0 + 4 + lt]);
        uint32_t a3 = __float_as_uint(Ss[(mrow + 8) * SS_ST + k0 + 4 + lt]);
        #pragma unroll
        for (int nt = 0; nt < 4; nt++) {
            const int nb = nh * 32 + nt * 8 + lg;   // output dim d
            uint32_t b0 = __float_as_uint(Vt[nb * VT_ST + k0 + lt]);
            uint32_t b1 = __float_as_uint(Vt[nb * VT_ST + k0 + 4 + lt]);
            mma_tf32(oc[nt], a0, a1, a2, a3, b0, b1);
        }
    }

    // ---- write output ----
    {
        const int row0 = b * T_SEQ + q0 + mrow;
        #pragma unroll
        for (int nt = 0; nt < 4; nt++) {
            const int col = hoff + nh * 32 + nt * 8 + lt * 2;
            *(float2*)(y + (size_t)row0 * EMB + col)
                = make_float2(oc[nt][0], oc[nt][1]);
            *(float2*)(y + (size_t)(row0 + 8) * EMB + col)
                = make_float2(oc[nt][2], oc[nt][3]);
        }
    }
}

// ---------------------------------------------------------------------------
// Launch
// ---------------------------------------------------------------------------
extern "C" void kernel_launch(void* const* d_in, const int* in_sizes, int n_in,
                              void* d_out, int out_size)
{
    const float* x      = (const float*)d_in[0];  // [128,256,384]
    const float* W_attn = (const float*)d_in[1];  // [384,1152]
    const float* b_attn = (const float*)d_in[2];  // [1152]
    const float* W_proj = (const float*)d_in[3];  // [384,384]
    const float* b_proj = (const float*)d_in[4];  // [384]
    float* out = (float*)d_out;                   // [128,256,384]

    float *qkv_ptr = nullptr, *y_ptr = nullptr;
    cudaGetSymbolAddress((void**)&qkv_ptr, g_qkv);
    cudaGetSymbolAddress((void**)&y_ptr, g_y);

    // 1) qkv = x @ W_attn + b_attn   (tf32 tensor cores)
    {
        dim3 grid(QKV_N / GBN, M_ROWS / GBM);
        gemm_tf32_kernel<<<grid, 256>>>(x, W_attn, b_attn, qkv_ptr, QKV_N);
    }

    // 2) banded attention (tensor cores) -> g_y
    {
        const int smem_bytes = SM_TOTF * (int)sizeof(float);   // 84 KB
        cudaFuncSetAttribute(attn_kernel, cudaFuncAttributeMaxDynamicSharedMemorySize, smem_bytes);
        dim3 grid(T_SEQ / QT, NH, B_SZ);
        attn_kernel<<<grid, 256, smem_bytes>>>(qkv_ptr, y_ptr);
    }

    // 3) out = y @ W_proj + b_proj   (tf32 tensor cores)
    {
        dim3 grid(EMB / GBN, M_ROWS / GBM);
        gemm_tf32_kernel<<<grid, 256>>>(y_ptr, W_proj, b_proj, out, EMB);
    }
}